// round 1
// baseline (speedup 1.0000x reference)
#include <cuda_runtime.h>

#define NROWS 500000
#define DIM 256
#define GSZ 32
#define NPHASES ((NROWS + GSZ - 1) / GSZ)

static __device__ __forceinline__ unsigned long long pack2(float a, float b){
  unsigned long long r; asm("mov.b64 %0,{%1,%2};":"=l"(r):"f"(a),"f"(b)); return r; }
static __device__ __forceinline__ void unpack2(unsigned long long v, float&a, float&b){
  asm("mov.b64 {%0,%1},%2;":"=f"(a),"=f"(b):"l"(v)); }
static __device__ __forceinline__ unsigned long long fma2(unsigned long long a, unsigned long long b, unsigned long long c){
  unsigned long long d; asm("fma.rn.f32x2 %0,%1,%2,%3;":"=l"(d):"l"(a),"l"(b),"l"(c)); return d; }
static __device__ __forceinline__ unsigned long long add2(unsigned long long a, unsigned long long b){
  unsigned long long d; asm("add.rn.f32x2 %0,%1,%2;":"=l"(d):"l"(a),"l"(b)); return d; }
static __device__ __forceinline__ float ex2f(float a){ float r; asm("ex2.approx.f32 %0,%1;":"=f"(r):"f"(a)); return r; }
static __device__ __forceinline__ float rcpf(float a){ float r; asm("rcp.approx.f32 %0,%1;":"=f"(r):"f"(a)); return r; }

// Two-warp warp-specialized fused kernel:
//   warp0: h = relu(x @ W1)  -> smem (double buffered, 32 rows/phase)
//   warp1: out = x * sigmoid(2 * (h @ W2))   [2*log2e folded into W2 regs]
// Weights live in registers (128 regs/lane each warp); x streamed via float4.
__global__ __launch_bounds__(64) void fb_kernel(
    const float* __restrict__ x, const float* __restrict__ W1,
    const float* __restrict__ W2, float* __restrict__ out)
{
  __shared__ float hbuf[2][GSZ][16];
  const int warp = threadIdx.x >> 5;
  const int lane = threadIdx.x & 31;

  int myPhases = 0;
  if ((int)blockIdx.x < NPHASES)
    myPhases = (NPHASES - 1 - (int)blockIdx.x) / (int)gridDim.x + 1;

  if (warp == 0) {
    // W1 slice for this lane: input cols [lane*8, lane*8+8), all 16 outputs,
    // stored as 8 packed f32x2 per input col (j-pairs are contiguous in W1).
    unsigned long long w1p[8][8];
    {
      const unsigned long long* w1u = (const unsigned long long*)W1;
      #pragma unroll
      for (int i = 0; i < 8; i++)
        #pragma unroll
        for (int p = 0; p < 8; p++)
          w1p[i][p] = __ldg(&w1u[(lane*8 + i)*8 + p]);
    }
    for (int it = 0; it <= myPhases; it++) {
      if (it < myPhases) {
        int phase = (int)blockIdx.x + it * (int)gridDim.x;
        int base = phase * GSZ;
        int rows = min(GSZ, NROWS - base);
        float* hb = &hbuf[it & 1][0][0];
        for (int r = 0; r < rows; r++) {
          const float4* xr = (const float4*)(x + (size_t)(base + r) * DIM) + lane*2;
          float4 a = __ldg(xr), b = __ldg(xr+1);
          float xs[8] = {a.x,a.y,a.z,a.w, b.x,b.y,b.z,b.w};
          unsigned long long acc[8];
          #pragma unroll
          for (int p=0;p<8;p++) acc[p] = 0ull;
          #pragma unroll
          for (int i=0;i<8;i++) {
            unsigned long long xi = pack2(xs[i], xs[i]);
            #pragma unroll
            for (int p=0;p<8;p++) acc[p] = fma2(xi, w1p[i][p], acc[p]);
          }
          // butterfly all-reduce of 16 partials (8 packed f32x2) over 32 lanes
          #pragma unroll
          for (int m=16;m>=1;m>>=1)
            #pragma unroll
            for (int p=0;p<8;p++)
              acc[p] = add2(acc[p], __shfl_xor_sync(0xffffffffu, acc[p], m));
          if (lane < 4) {
            float h0,h1,h2,h3;
            unpack2(acc[2*lane],   h0, h1);
            unpack2(acc[2*lane+1], h2, h3);
            float4 hv = make_float4(fmaxf(h0,0.f), fmaxf(h1,0.f),
                                    fmaxf(h2,0.f), fmaxf(h3,0.f));
            *(float4*)(hb + r*16 + lane*4) = hv;
          }
        }
      }
      __syncthreads();
    }
  } else {
    // W2 slice for this lane: output cols [lane*8, lane*8+8), all 16 inputs,
    // pre-scaled by -2*log2(e) so acc = -s*log2(e); sigmoid = rcp(1 + ex2(acc)).
    unsigned long long w2p[16][4];
    {
      const float c = -2.0f * 1.4426950408889634f;
      #pragma unroll
      for (int j = 0; j < 16; j++)
        #pragma unroll
        for (int p = 0; p < 4; p++) {
          float a = __ldg(&W2[j*DIM + lane*8 + 2*p])     * c;
          float b = __ldg(&W2[j*DIM + lane*8 + 2*p + 1]) * c;
          w2p[j][p] = pack2(a, b);
        }
    }
    for (int it = 0; it <= myPhases; it++) {
      if (it >= 1) {
        int phase = (int)blockIdx.x + (it-1) * (int)gridDim.x;
        int base = phase * GSZ;
        int rows = min(GSZ, NROWS - base);
        const float* hb = &hbuf[(it-1) & 1][0][0];
        for (int r = 0; r < rows; r++) {
          float4 h0 = *(const float4*)(hb + r*16);
          float4 h1 = *(const float4*)(hb + r*16 + 4);
          float4 h2 = *(const float4*)(hb + r*16 + 8);
          float4 h3 = *(const float4*)(hb + r*16 + 12);
          float hv[16] = {h0.x,h0.y,h0.z,h0.w, h1.x,h1.y,h1.z,h1.w,
                          h2.x,h2.y,h2.z,h2.w, h3.x,h3.y,h3.z,h3.w};
          unsigned long long acc[4];
          #pragma unroll
          for (int p=0;p<4;p++) acc[p] = 0ull;
          #pragma unroll
          for (int j=0;j<16;j++) {
            unsigned long long hj = pack2(hv[j], hv[j]);
            #pragma unroll
            for (int p=0;p<4;p++) acc[p] = fma2(hj, w2p[j][p], acc[p]);
          }
          const float4* xr = (const float4*)(x + (size_t)(base + r) * DIM) + lane*2;
          float4 xa = __ldg(xr), xb = __ldg(xr+1);
          float sg[8];
          #pragma unroll
          for (int p=0;p<4;p++) {
            float t0,t1; unpack2(acc[p], t0, t1);
            sg[2*p]   = rcpf(1.0f + ex2f(t0));
            sg[2*p+1] = rcpf(1.0f + ex2f(t1));
          }
          float4 o0 = make_float4(xa.x*sg[0], xa.y*sg[1], xa.z*sg[2], xa.w*sg[3]);
          float4 o1 = make_float4(xb.x*sg[4], xb.y*sg[5], xb.z*sg[6], xb.w*sg[7]);
          float4* orow = (float4*)(out + (size_t)(base + r) * DIM) + lane*2;
          orow[0] = o0; orow[1] = o1;
        }
      }
      __syncthreads();
    }
  }
}

extern "C" void kernel_launch(void* const* d_in, const int* in_sizes, int n_in,
                              void* d_out, int out_size) {
  const float* x  = (const float*)d_in[0];
  const float* W1 = (const float*)d_in[1];
  const float* W2 = (const float*)d_in[2];
  float* out = (float*)d_out;
  fb_kernel<<<1480, 64>>>(x, W1, W2, out);
}

// round 3
// speedup vs baseline: 1.8414x; 1.8414x over previous
#include <cuda_runtime.h>

#define NROWS 500000
#define DIM 256
#define GSZ 32
#define NPHASES ((NROWS + GSZ - 1) / GSZ)   // 15625 phases of 32 rows

static __device__ __forceinline__ unsigned long long pack2(float a, float b){
  unsigned long long r; asm("mov.b64 %0,{%1,%2};":"=l"(r):"f"(a),"f"(b)); return r; }
static __device__ __forceinline__ void unpack2(unsigned long long v, float&a, float&b){
  asm("mov.b64 {%0,%1},%2;":"=f"(a),"=f"(b):"l"(v)); }
static __device__ __forceinline__ unsigned long long fma2(unsigned long long a, unsigned long long b, unsigned long long c){
  unsigned long long d; asm("fma.rn.f32x2 %0,%1,%2,%3;":"=l"(d):"l"(a),"l"(b),"l"(c)); return d; }
static __device__ __forceinline__ unsigned long long add2(unsigned long long a, unsigned long long b){
  unsigned long long d; asm("add.rn.f32x2 %0,%1,%2;":"=l"(d):"l"(a),"l"(b)); return d; }
static __device__ __forceinline__ float ex2f(float a){ float r; asm("ex2.approx.f32 %0,%1;":"=f"(r):"f"(a)); return r; }
static __device__ __forceinline__ float rcpf(float a){ float r; asm("rcp.approx.f32 %0,%1;":"=f"(r):"f"(a)); return r; }

// 128-thread CTA = 2 independent warp-pairs, warps 0..3 cover all 4 SMSPs.
//   even warp (role 0): h = relu(x @ W1) -> smem (reduce-scatter, double buffered)
//   odd  warp (role 1): out = x * sigmoid(2*(h @ W2))   [-2*log2e folded into W2]
__global__ __launch_bounds__(128, 3) void fb_kernel(
    const float* __restrict__ x, const float* __restrict__ W1,
    const float* __restrict__ W2, float* __restrict__ out)
{
  __shared__ float hbuf[2][2][GSZ][16];   // [pair][buf][row][h]
  const int warp = threadIdx.x >> 5;
  const int lane = threadIdx.x & 31;
  const int pair = warp >> 1;
  const int role = warp & 1;
  const int vb = (int)blockIdx.x * 2 + pair;        // virtual stream id
  const int nstreams = (int)gridDim.x * 2;

  int myPhases = 0;
  if (vb < NPHASES) myPhases = (NPHASES - 1 - vb) / nstreams + 1;

  if (role == 0) {
    // W1 slice: input cols [lane*8, lane*8+8), all 16 outputs, packed j-pairs.
    unsigned long long w1p[8][8];
    {
      const unsigned long long* w1u = (const unsigned long long*)W1;
      #pragma unroll
      for (int i = 0; i < 8; i++)
        #pragma unroll
        for (int p = 0; p < 8; p++)
          w1p[i][p] = __ldg(&w1u[(lane*8 + i)*8 + p]);
    }
    for (int it = 0; it <= myPhases; it++) {
      if (it < myPhases) {
        int phase = vb + it * nstreams;
        int base = phase * GSZ;
        int rows = min(GSZ, NROWS - base);
        float* hb = &hbuf[pair][it & 1][0][0];
        #pragma unroll 1
        for (int r = 0; r < rows; r++) {
          // L2 prefetch 4 rows ahead (covers DRAM latency; no register cost)
          {
            int pr = base + r + 4; if (pr >= NROWS) pr = NROWS - 1;
            asm volatile("prefetch.global.L2 [%0];" :: "l"(x + (size_t)pr * DIM + lane*8));
          }
          const float4* xr = (const float4*)(x + (size_t)(base + r) * DIM) + lane*2;
          float4 a = __ldg(xr), b = __ldg(xr+1);
          float xs[8] = {a.x,a.y,a.z,a.w, b.x,b.y,b.z,b.w};
          unsigned long long acc[8];
          #pragma unroll
          for (int p=0;p<8;p++) acc[p] = 0ull;
          #pragma unroll
          for (int i=0;i<8;i++) {
            unsigned long long xi = pack2(xs[i], xs[i]);
            #pragma unroll
            for (int p=0;p<8;p++) acc[p] = fma2(xi, w1p[i][p], acc[p]);
          }
          // reduce-scatter: send the half I'm NOT keeping, keep my half.
          bool s16 = (lane & 16) != 0;
          bool s8  = (lane & 8)  != 0;
          bool s4  = (lane & 4)  != 0;
          #pragma unroll
          for (int p=0;p<4;p++) {
            unsigned long long send = s16 ? acc[p]   : acc[p+4];
            unsigned long long keep = s16 ? acc[p+4] : acc[p];
            acc[p] = add2(keep, __shfl_xor_sync(0xffffffffu, send, 16));
          }
          #pragma unroll
          for (int p=0;p<2;p++) {
            unsigned long long send = s8 ? acc[p]   : acc[p+2];
            unsigned long long keep = s8 ? acc[p+2] : acc[p];
            acc[p] = add2(keep, __shfl_xor_sync(0xffffffffu, send, 8));
          }
          {
            unsigned long long send = s4 ? acc[0] : acc[1];
            unsigned long long keep = s4 ? acc[1] : acc[0];
            acc[0] = add2(keep, __shfl_xor_sync(0xffffffffu, send, 4));
          }
          acc[0] = add2(acc[0], __shfl_xor_sync(0xffffffffu, acc[0], 2));
          acc[0] = add2(acc[0], __shfl_xor_sync(0xffffffffu, acc[0], 1));
          float h0, h1; unpack2(acc[0], h0, h1);
          h0 = fmaxf(h0, 0.f); h1 = fmaxf(h1, 0.f);
          if ((lane & 3) == 0) {
            // pair index = s16*4 + s8*2 + s4 ; element offset = 2*pair
            int bix = ((lane>>2)&1)*2 + ((lane>>3)&1)*4 + ((lane>>4)&1)*8;
            *(float2*)(hb + r*16 + bix) = make_float2(h0, h1);
          }
        }
      }
      asm volatile("bar.sync %0, 64;" :: "r"(1 + pair) : "memory");
    }
  } else {
    // W2 slice: output cols [lane*8, lane*8+8), all 16 inputs, pre-scaled by
    // -2*log2(e):  sigmoid(2m) = rcp(1 + ex2(-2m*log2e)).
    unsigned long long w2p[16][4];
    {
      const float c = -2.0f * 1.4426950408889634f;
      #pragma unroll
      for (int j = 0; j < 16; j++)
        #pragma unroll
        for (int p = 0; p < 4; p++) {
          float a = __ldg(&W2[j*DIM + lane*8 + 2*p])     * c;
          float b = __ldg(&W2[j*DIM + lane*8 + 2*p + 1]) * c;
          w2p[j][p] = pack2(a, b);
        }
    }
    for (int it = 0; it <= myPhases; it++) {
      if (it >= 1) {
        int phase = vb + (it-1) * nstreams;
        int base = phase * GSZ;
        int rows = min(GSZ, NROWS - base);
        const float* hb = &hbuf[pair][(it-1) & 1][0][0];
        #pragma unroll 1
        for (int r = 0; r < rows; r++) {
          unsigned long long acc[4];
          #pragma unroll
          for (int p=0;p<4;p++) acc[p] = 0ull;
          #pragma unroll
          for (int jj = 0; jj < 4; jj++) {
            float4 h4 = *(const float4*)(hb + r*16 + jj*4);
            float hv[4] = {h4.x, h4.y, h4.z, h4.w};
            #pragma unroll
            for (int q = 0; q < 4; q++) {
              unsigned long long hj = pack2(hv[q], hv[q]);
              #pragma unroll
              for (int p=0;p<4;p++) acc[p] = fma2(hj, w2p[jj*4+q][p], acc[p]);
            }
          }
          const float4* xr = (const float4*)(x + (size_t)(base + r) * DIM) + lane*2;
          float4 xa = __ldg(xr), xb = __ldg(xr+1);
          float sg[8];
          #pragma unroll
          for (int p=0;p<4;p++) {
            float t0,t1; unpack2(acc[p], t0, t1);
            sg[2*p]   = rcpf(1.0f + ex2f(t0));
            sg[2*p+1] = rcpf(1.0f + ex2f(t1));
          }
          float4 o0 = make_float4(xa.x*sg[0], xa.y*sg[1], xa.z*sg[2], xa.w*sg[3]);
          float4 o1 = make_float4(xb.x*sg[4], xb.y*sg[5], xb.z*sg[6], xb.w*sg[7]);
          float4* orow = (float4*)(out + (size_t)(base + r) * DIM) + lane*2;
          orow[0] = o0; orow[1] = o1;
        }
      }
      asm volatile("bar.sync %0, 64;" :: "r"(1 + pair) : "memory");
    }
  }
}

extern "C" void kernel_launch(void* const* d_in, const int* in_sizes, int n_in,
                              void* d_out, int out_size) {
  const float* x  = (const float*)d_in[0];
  const float* W1 = (const float*)d_in[1];
  const float* W2 = (const float*)d_in[2];
  float* out = (float*)d_out;
  fb_kernel<<<444, 128>>>(x, W1, W2, out);
}